// round 2
// baseline (speedup 1.0000x reference)
#include <cuda_runtime.h>
#include <cuda_bf16.h>
#include <cstdint>

// Problem constants (fixed shapes per reference)
#define NMAX   50000
#define DIMC   256
#define NHEAD  8
#define HDIM   32
#define KNBR   16
#define QSCALE 0.17677669529663689f   // 1/sqrt(32)

// Scratch (device globals — no allocation allowed in kernel_launch)
__device__ float g_q[(size_t)NMAX * DIMC];
__device__ float g_k[(size_t)NMAX * DIMC];
__device__ float g_v[(size_t)NMAX * DIMC];
__device__ float g_x[(size_t)NMAX * DIMC];

// ---------------------------------------------------------------------------
// GEMM: C[M, Ncols] = A[M,256] @ W[Ncols,256]^T + bias   (both K-contiguous)
// Tile 64x64, BK=64, 256 threads, 4x4 per thread micro-tile.
// SPLIT=1: Ncols=768, write q (scaled) / k / v device globals.
// SPLIT=0: A is g_x, Ncols=256, write C directly.
// ---------------------------------------------------------------------------
template <int SPLIT>
__global__ void __launch_bounds__(256) gemm_nt(const float* __restrict__ A,
                                               const float* __restrict__ W,
                                               const float* __restrict__ bias,
                                               float* __restrict__ C,
                                               int M)
{
    __shared__ float As[64][65];
    __shared__ float Bs[64][65];

    const int t  = threadIdx.x;
    const int tx = t & 15;
    const int ty = t >> 4;

    const int m0 = blockIdx.x * 64;
    const int n0 = blockIdx.y * 64;

    const float* Aeff = SPLIT ? A : g_x;

    float acc[4][4];
#pragma unroll
    for (int r = 0; r < 4; r++)
#pragma unroll
        for (int c = 0; c < 4; c++) acc[r][c] = 0.f;

    for (int kc = 0; kc < 256; kc += 64) {
        // load A tile (guard rows) and W tile, as float4, store scalar (m-major)
#pragma unroll
        for (int p = 0; p < 4; p++) {
            int idx = t + p * 256;          // 0..1023
            int row = idx >> 4;             // 0..63
            int c4  = idx & 15;             // float4 index 0..15
            float4 av = make_float4(0.f, 0.f, 0.f, 0.f);
            if (m0 + row < M)
                av = reinterpret_cast<const float4*>(Aeff + (size_t)(m0 + row) * 256 + kc)[c4];
            As[row][c4 * 4 + 0] = av.x;
            As[row][c4 * 4 + 1] = av.y;
            As[row][c4 * 4 + 2] = av.z;
            As[row][c4 * 4 + 3] = av.w;

            float4 bv = reinterpret_cast<const float4*>(W + (size_t)(n0 + row) * 256 + kc)[c4];
            Bs[row][c4 * 4 + 0] = bv.x;
            Bs[row][c4 * 4 + 1] = bv.y;
            Bs[row][c4 * 4 + 2] = bv.z;
            Bs[row][c4 * 4 + 3] = bv.w;
        }
        __syncthreads();

#pragma unroll 16
        for (int kk = 0; kk < 64; kk++) {
            float a0 = As[ty * 4 + 0][kk];
            float a1 = As[ty * 4 + 1][kk];
            float a2 = As[ty * 4 + 2][kk];
            float a3 = As[ty * 4 + 3][kk];
            float b0 = Bs[tx * 4 + 0][kk];
            float b1 = Bs[tx * 4 + 1][kk];
            float b2 = Bs[tx * 4 + 2][kk];
            float b3 = Bs[tx * 4 + 3][kk];
            acc[0][0] += a0 * b0; acc[0][1] += a0 * b1; acc[0][2] += a0 * b2; acc[0][3] += a0 * b3;
            acc[1][0] += a1 * b0; acc[1][1] += a1 * b1; acc[1][2] += a1 * b2; acc[1][3] += a1 * b3;
            acc[2][0] += a2 * b0; acc[2][1] += a2 * b1; acc[2][2] += a2 * b2; acc[2][3] += a2 * b3;
            acc[3][0] += a3 * b0; acc[3][1] += a3 * b1; acc[3][2] += a3 * b2; acc[3][3] += a3 * b3;
        }
        __syncthreads();
    }

    const int col0 = n0 + tx * 4;
    float bv[4];
#pragma unroll
    for (int c = 0; c < 4; c++) bv[c] = bias[col0 + c];

    if (SPLIT) {
        const int sect = blockIdx.y >> 2;            // 0=q, 1=k, 2=v (uniform per block)
        float* dst = (sect == 0) ? g_q : (sect == 1) ? g_k : g_v;
        const float mult = (sect == 0) ? QSCALE : 1.0f;
        const int colq = col0 - sect * 256;
#pragma unroll
        for (int r = 0; r < 4; r++) {
            int row = m0 + ty * 4 + r;
            if (row < M) {
#pragma unroll
                for (int c = 0; c < 4; c++)
                    dst[(size_t)row * 256 + colq + c] = (acc[r][c] + bv[c]) * mult;
            }
        }
    } else {
#pragma unroll
        for (int r = 0; r < 4; r++) {
            int row = m0 + ty * 4 + r;
            if (row < M) {
#pragma unroll
                for (int c = 0; c < 4; c++)
                    C[(size_t)row * 256 + col0 + c] = acc[r][c] + bv[c];
            }
        }
    }
}

// ---------------------------------------------------------------------------
// Per-point attention: one block (256 threads) per point.
// Phase 1 (threads 0..127, t = h*16 + j): logits + 16-lane softmax via shfl.
// Phase 2 (all 256, t = h*32 + d): x[i,h,d] = sum_j w[h][j] * v[nbr[j],h,d].
// ---------------------------------------------------------------------------
__global__ void __launch_bounds__(256) attn_kernel(const int* __restrict__ index_1, int M)
{
    const int i = blockIdx.x;
    if (i >= M) return;

    __shared__ __align__(16) float q_s[256];
    __shared__ int   nbr[16];
    __shared__ float w_s[8][16];

    const int t = threadIdx.x;

    q_s[t] = g_q[(size_t)i * 256 + t];
    if (t < 16) nbr[t] = index_1[i * KNBR + t];
    __syncthreads();

    if (t < 128) {
        const int h = t >> 4;
        const int j = t & 15;
        const float4* kr = reinterpret_cast<const float4*>(g_k + (size_t)nbr[j] * 256 + h * 32);
        const float4* qh = reinterpret_cast<const float4*>(q_s + h * 32);
        float dot = 0.f;
#pragma unroll
        for (int d4 = 0; d4 < 8; d4++) {
            float4 kv = kr[d4];
            float4 qv = qh[d4];
            dot += qv.x * kv.x + qv.y * kv.y + qv.z * kv.z + qv.w * kv.w;
        }
        // softmax over the 16-lane group (xor offsets 8,4,2,1 stay within group)
        float mx = dot;
#pragma unroll
        for (int o = 8; o > 0; o >>= 1) mx = fmaxf(mx, __shfl_xor_sync(0xffffffffu, mx, o));
        float e = __expf(dot - mx);
        float s = e;
#pragma unroll
        for (int o = 8; o > 0; o >>= 1) s += __shfl_xor_sync(0xffffffffu, s, o);
        w_s[h][j] = e / s;
    }
    __syncthreads();

    const int h = t >> 5;
    const int d = t & 31;
    const float* vb = g_v + h * 32 + d;
    float acc = 0.f;
#pragma unroll
    for (int j = 0; j < 16; j++)
        acc += w_s[h][j] * vb[(size_t)nbr[j] * 256];

    g_x[(size_t)i * 256 + t] = acc;
}

// ---------------------------------------------------------------------------
// Input order (metadata): feats, xyz, index_0, index_1, index_0_offsets,
//                         n_max, qkv_w, qkv_b, proj_w, proj_b
// Weights located robustly by size (qkv_w = 3*256*256 = 196608).
// ---------------------------------------------------------------------------
extern "C" void kernel_launch(void* const* d_in, const int* in_sizes, int n_in,
                              void* d_out, int out_size)
{
    const float* feats   = (const float*)d_in[0];
    const int*   index_1 = (const int*)d_in[3];

    int iw = -1;
    for (int i = 0; i < n_in; i++) {
        if (in_sizes[i] == 3 * DIMC * DIMC) { iw = i; break; }
    }
    const float* qkv_w  = (const float*)d_in[iw];
    const float* qkv_b  = (const float*)d_in[iw + 1];
    const float* proj_w = (const float*)d_in[iw + 2];
    const float* proj_b = (const float*)d_in[iw + 3];

    const int M = in_sizes[0] / DIMC;   // 50000

    dim3 g_qkv((M + 63) / 64, 12);      // 768 output channels
    gemm_nt<1><<<g_qkv, 256>>>(feats, qkv_w, qkv_b, nullptr, M);

    attn_kernel<<<M, 256>>>(index_1, M);

    dim3 g_proj((M + 63) / 64, 4);      // 256 output channels
    gemm_nt<0><<<g_proj, 256>>>(nullptr, proj_w, proj_b, (float*)d_out, M);
}

// round 8
// speedup vs baseline: 2.9817x; 2.9817x over previous
#include <cuda_runtime.h>
#include <cuda_bf16.h>
#include <cstdint>

#define NMAX   50000
#define DIMC   256
#define KNBR   16
#define QSCALE 0.17677669529663689f   // 1/sqrt(32)

// ---------------- device scratch (no allocations allowed) -------------------
__device__ __nv_bfloat16 f_hi[(size_t)NMAX * DIMC];
__device__ __nv_bfloat16 f_lo[(size_t)NMAX * DIMC];
__device__ __nv_bfloat16 w_hi[768 * 256];
__device__ __nv_bfloat16 w_lo[768 * 256];
__device__ __nv_bfloat16 pw_hi[256 * 256];
__device__ __nv_bfloat16 pw_lo[256 * 256];
__device__ float g_q[(size_t)NMAX * DIMC];
__device__ float g_k[(size_t)NMAX * DIMC];
__device__ float g_v[(size_t)NMAX * DIMC];
__device__ __nv_bfloat16 x_hi[(size_t)NMAX * DIMC];
__device__ __nv_bfloat16 x_lo[(size_t)NMAX * DIMC];

// ---------------- helpers ---------------------------------------------------
__device__ __forceinline__ uint32_t smem_u32(const void* p) {
    uint32_t a;
    asm("{ .reg .u64 t; cvta.to.shared.u64 t, %1; cvt.u32.u64 %0, t; }" : "=r"(a) : "l"(p));
    return a;
}

// fp32 -> (bf16 hi, bf16 lo) split.  which: 0=feats, 1=qkv_w, 2=proj_w
__global__ void cvt_hilo(const float* __restrict__ src, int which, int n) {
    int i = blockIdx.x * blockDim.x + threadIdx.x;
    if (i >= n) return;
    __nv_bfloat16* hi = (which == 0) ? f_hi : (which == 1) ? w_hi : pw_hi;
    __nv_bfloat16* lo = (which == 0) ? f_lo : (which == 1) ? w_lo : pw_lo;
    float x = src[i];
    __nv_bfloat16 h = __float2bfloat16(x);
    hi[i] = h;
    lo[i] = __float2bfloat16(x - __bfloat162float(h));
}

// ---------------------------------------------------------------------------
// Split-bf16 GEMM on mma.sync (m16n8k16, bf16 in / fp32 acc).
// C[M,Ncols] = A[M,256] @ W[Ncols,256]^T + bias, via 3 products:
//   Ah*Bh + Ah*Bl + Al*Bh   (fp32 accumulated, ~16 effective mantissa bits)
// Block tile 128x128, 8 warps (4x2), warp tile 32x64. K-chunks of 64.
// SMEM rows are 128B (64 bf16) with SW128 xor swizzle; since the k-byte
// offset < 128, the xor mask reduces to (row&7)*16.
// SPLIT=1: A=f_hi/lo, W=w_hi/lo (768 cols) -> g_q(*QSCALE)/g_k/g_v
// SPLIT=0: A=x_hi/lo, W=pw_hi/lo (256 cols) -> Cout
// ---------------------------------------------------------------------------
template <int SPLIT>
__global__ void __launch_bounds__(256) gemm_mma(const float* __restrict__ bias,
                                                float* __restrict__ Cout, int M)
{
    __shared__ __align__(1024) __nv_bfloat16 As[128 * 64];
    __shared__ __align__(1024) __nv_bfloat16 Bs[128 * 64];

    const int t    = threadIdx.x;
    const int lane = t & 31;
    const int w    = t >> 5;
    const int wm   = w & 3;           // 4 warps over M (32 rows each)
    const int wn   = w >> 2;          // 2 warps over N (64 cols each)
    const int m0   = blockIdx.x * 128;
    const int n0   = blockIdx.y * 128;

    const uint32_t sbA = smem_u32(As);
    const uint32_t sbB = smem_u32(Bs);

    const __nv_bfloat16* Ah = SPLIT ? f_hi : x_hi;
    const __nv_bfloat16* Al = SPLIT ? f_lo : x_lo;
    const __nv_bfloat16* Bh = SPLIT ? w_hi : pw_hi;
    const __nv_bfloat16* Bl = SPLIT ? w_lo : pw_lo;

    // gmem->smem mapping: thread handles row = t>>1, 64B half = t&1 (4 x 16B)
    const int ldRow  = t >> 1;
    const int ldHalf = t & 1;
    const bool a_ok  = (m0 + ldRow) < M;
    const uint32_t ldXor = (uint32_t)((ldRow & 7) * 16);

    // ldmatrix address components (constant per thread)
    // A frag (m16k16, x4): lanes0-15 rows 0-15 @kb, lanes16-31 rows 0-15 @kb+16
    const int aRowIn  = lane & 15;
    const int aKbAdd  = (lane >> 4) * 16;
    // B frag pair (2x n8k16, x4): n = (lane&7) + (lane>>4)*8, kb += ((lane>>3)&1)*16
    const int bNIn    = (lane & 7) + ((lane >> 4) << 3);
    const int bKbAdd  = ((lane >> 3) & 1) * 16;

    float acc[2][8][4];
#pragma unroll
    for (int f = 0; f < 2; f++)
#pragma unroll
        for (int g = 0; g < 8; g++)
#pragma unroll
            for (int e = 0; e < 4; e++) acc[f][g][e] = 0.f;

#pragma unroll 1
    for (int p = 0; p < 3; p++) {
        const __nv_bfloat16* Ap = (p == 2) ? Al : Ah;
        const __nv_bfloat16* Bp = (p == 1) ? Bl : Bh;

#pragma unroll 1
        for (int c = 0; c < 4; c++) {
            __syncthreads();
            // ---- load 128x64 A and B chunks into swizzled smem ----
            {
                const size_t gA = (size_t)(m0 + ldRow) * 256 + c * 64 + ldHalf * 32;
                const size_t gB = (size_t)(n0 + ldRow) * 256 + c * 64 + ldHalf * 32;
                const uint4* pA = reinterpret_cast<const uint4*>(Ap + gA);
                const uint4* pB = reinterpret_cast<const uint4*>(Bp + gB);
                const uint4 z = make_uint4(0, 0, 0, 0);
#pragma unroll
                for (int j = 0; j < 4; j++) {
                    uint32_t cb = (uint32_t)(ldHalf * 64 + j * 16);
                    uint32_t so = (uint32_t)(ldRow * 128) + (cb ^ ldXor);
                    *reinterpret_cast<uint4*>(reinterpret_cast<char*>(As) + so) = a_ok ? pA[j] : z;
                    *reinterpret_cast<uint4*>(reinterpret_cast<char*>(Bs) + so) = pB[j];
                }
            }
            __syncthreads();

            // ---- 4 k-steps of 16 ----
#pragma unroll
            for (int ks = 0; ks < 4; ks++) {
                const uint32_t kByte = (uint32_t)(ks * 32);

                uint32_t af[2][4];
#pragma unroll
                for (int f = 0; f < 2; f++) {
                    int row = wm * 32 + f * 16 + aRowIn;
                    uint32_t kb = kByte + (uint32_t)aKbAdd;
                    uint32_t addr = sbA + (uint32_t)(row * 128) + (kb ^ (uint32_t)((row & 7) * 16));
                    asm volatile("ldmatrix.sync.aligned.m8n8.x4.shared.b16 {%0,%1,%2,%3}, [%4];"
                                 : "=r"(af[f][0]), "=r"(af[f][1]), "=r"(af[f][2]), "=r"(af[f][3])
                                 : "r"(addr));
                }

                uint32_t bf_[4][4];
#pragma unroll
                for (int g2 = 0; g2 < 4; g2++) {
                    int nb = wn * 64 + g2 * 16 + bNIn;
                    uint32_t kb = kByte + (uint32_t)bKbAdd;
                    uint32_t addr = sbB + (uint32_t)(nb * 128) + (kb ^ (uint32_t)((nb & 7) * 16));
                    asm volatile("ldmatrix.sync.aligned.m8n8.x4.shared.b16 {%0,%1,%2,%3}, [%4];"
                                 : "=r"(bf_[g2][0]), "=r"(bf_[g2][1]), "=r"(bf_[g2][2]), "=r"(bf_[g2][3])
                                 : "r"(addr));
                }

#pragma unroll
                for (int f = 0; f < 2; f++) {
#pragma unroll
                    for (int g2 = 0; g2 < 4; g2++) {
                        asm volatile(
                            "mma.sync.aligned.m16n8k16.row.col.f32.bf16.bf16.f32 "
                            "{%0,%1,%2,%3}, {%4,%5,%6,%7}, {%8,%9}, {%0,%1,%2,%3};"
                            : "+f"(acc[f][g2 * 2][0]), "+f"(acc[f][g2 * 2][1]),
                              "+f"(acc[f][g2 * 2][2]), "+f"(acc[f][g2 * 2][3])
                            : "r"(af[f][0]), "r"(af[f][1]), "r"(af[f][2]), "r"(af[f][3]),
                              "r"(bf_[g2][0]), "r"(bf_[g2][1]));
                        asm volatile(
                            "mma.sync.aligned.m16n8k16.row.col.f32.bf16.bf16.f32 "
                            "{%0,%1,%2,%3}, {%4,%5,%6,%7}, {%8,%9}, {%0,%1,%2,%3};"
                            : "+f"(acc[f][g2 * 2 + 1][0]), "+f"(acc[f][g2 * 2 + 1][1]),
                              "+f"(acc[f][g2 * 2 + 1][2]), "+f"(acc[f][g2 * 2 + 1][3])
                            : "r"(af[f][0]), "r"(af[f][1]), "r"(af[f][2]), "r"(af[f][3]),
                              "r"(bf_[g2][2]), "r"(bf_[g2][3]));
                    }
                }
            }
        }
    }

    // ---- epilogue ----
    // acc frag layout (m16n8): c0,c1 -> row lane/4,     cols 2*(lane&3)+{0,1}
    //                          c2,c3 -> row lane/4 + 8, same cols
    const int rBase = m0 + wm * 32 + (lane >> 2);
    const int cIn   = (lane & 3) * 2;

    const int sect = SPLIT ? (n0 >> 8) : 0;
    float* dstBase = SPLIT ? ((sect == 0) ? g_q : (sect == 1) ? g_k : g_v) : Cout;
    const float mult = (SPLIT && sect == 0) ? QSCALE : 1.0f;
    const int nLocal = SPLIT ? (n0 & 255) : n0;

#pragma unroll
    for (int f = 0; f < 2; f++) {
#pragma unroll
        for (int g = 0; g < 8; g++) {
            const int colFull = n0 + wn * 64 + g * 8 + cIn;       // for bias
            const int colOut  = nLocal + wn * 64 + g * 8 + cIn;   // for dst
            const float b0 = bias[colFull], b1 = bias[colFull + 1];
#pragma unroll
            for (int h = 0; h < 2; h++) {
                const int row = rBase + f * 16 + h * 8;
                if (row < M) {
                    float2 ov;
                    ov.x = (acc[f][g][h * 2 + 0] + b0) * mult;
                    ov.y = (acc[f][g][h * 2 + 1] + b1) * mult;
                    *reinterpret_cast<float2*>(dstBase + (size_t)row * 256 + colOut) = ov;
                }
            }
        }
    }
}

// ---------------------------------------------------------------------------
// Per-point attention: one block (256 threads) per point. Writes x as hi/lo bf16.
// ---------------------------------------------------------------------------
__global__ void __launch_bounds__(256) attn_kernel(const int* __restrict__ index_1, int M)
{
    const int i = blockIdx.x;
    if (i >= M) return;

    __shared__ __align__(16) float q_s[256];
    __shared__ int   nbr[16];
    __shared__ float w_s[8][16];

    const int t = threadIdx.x;

    q_s[t] = g_q[(size_t)i * 256 + t];
    if (t < 16) nbr[t] = index_1[i * KNBR + t];
    __syncthreads();

    if (t < 128) {
        const int h = t >> 4;
        const int j = t & 15;
        const float4* kr = reinterpret_cast<const float4*>(g_k + (size_t)nbr[j] * 256 + h * 32);
        const float4* qh = reinterpret_cast<const float4*>(q_s + h * 32);
        float dot = 0.f;
#pragma unroll
        for (int d4 = 0; d4 < 8; d4++) {
            float4 kv = kr[d4];
            float4 qv = qh[d4];
            dot += qv.x * kv.x + qv.y * kv.y + qv.z * kv.z + qv.w * kv.w;
        }
        float mx = dot;
#pragma unroll
        for (int o = 8; o > 0; o >>= 1) mx = fmaxf(mx, __shfl_xor_sync(0xffffffffu, mx, o));
        float e = __expf(dot - mx);
        float s = e;
#pragma unroll
        for (int o = 8; o > 0; o >>= 1) s += __shfl_xor_sync(0xffffffffu, s, o);
        w_s[h][j] = e / s;
    }
    __syncthreads();

    const int h = t >> 5;
    const int d = t & 31;
    const float* vb = g_v + h * 32 + d;
    float acc = 0.f;
#pragma unroll
    for (int j = 0; j < 16; j++)
        acc += w_s[h][j] * vb[(size_t)nbr[j] * 256];

    __nv_bfloat16 hv = __float2bfloat16(acc);
    x_hi[(size_t)i * 256 + t] = hv;
    x_lo[(size_t)i * 256 + t] = __float2bfloat16(acc - __bfloat162float(hv));
}

// ---------------------------------------------------------------------------
extern "C" void kernel_launch(void* const* d_in, const int* in_sizes, int n_in,
                              void* d_out, int out_size)
{
    const float* feats   = (const float*)d_in[0];
    const int*   index_1 = (const int*)d_in[3];

    int iw = -1;
    for (int i = 0; i < n_in; i++)
        if (in_sizes[i] == 3 * DIMC * DIMC) { iw = i; break; }
    const float* qkv_w  = (const float*)d_in[iw];
    const float* qkv_b  = (const float*)d_in[iw + 1];
    const float* proj_w = (const float*)d_in[iw + 2];
    const float* proj_b = (const float*)d_in[iw + 3];

    const int M = in_sizes[0] / DIMC;   // 50000

    cvt_hilo<<<(M * DIMC + 255) / 256, 256>>>(feats, 0, M * DIMC);
    cvt_hilo<<<(768 * 256 + 255) / 256, 256>>>(qkv_w, 1, 768 * 256);
    cvt_hilo<<<(256 * 256 + 255) / 256, 256>>>(proj_w, 2, 256 * 256);

    dim3 g_qkv((M + 127) / 128, 6);     // 768 output cols
    gemm_mma<1><<<g_qkv, 256>>>(qkv_b, nullptr, M);

    attn_kernel<<<M, 256>>>(index_1, M);

    dim3 g_proj((M + 127) / 128, 2);    // 256 output cols
    gemm_mma<0><<<g_proj, 256>>>(proj_b, (float*)d_out, M);
}

// round 11
// speedup vs baseline: 3.4840x; 1.1685x over previous
#include <cuda_runtime.h>
#include <cuda_bf16.h>
#include <cstdint>

#define NMAX   50000
#define DIMC   256
#define KNBR   16
#define QSCALE 0.17677669529663689f   // 1/sqrt(32)

// ---------------- device scratch (no allocations allowed) -------------------
__device__ __nv_bfloat16 f_hi[(size_t)NMAX * DIMC];
__device__ __nv_bfloat16 f_lo[(size_t)NMAX * DIMC];
__device__ __nv_bfloat16 w_hi[768 * 256];
__device__ __nv_bfloat16 w_lo[768 * 256];
__device__ __nv_bfloat16 pw_hi[256 * 256];
__device__ __nv_bfloat16 pw_lo[256 * 256];
__device__ float g_q[(size_t)NMAX * DIMC];
__device__ float g_k[(size_t)NMAX * DIMC];
__device__ float g_v[(size_t)NMAX * DIMC];
__device__ __nv_bfloat16 x_hi[(size_t)NMAX * DIMC];
__device__ __nv_bfloat16 x_lo[(size_t)NMAX * DIMC];

// ---------------- helpers ---------------------------------------------------
__device__ __forceinline__ uint32_t smem_u32(const void* p) {
    uint32_t a;
    asm("{ .reg .u64 t; cvta.to.shared.u64 t, %1; cvt.u32.u64 %0, t; }" : "=r"(a) : "l"(p));
    return a;
}
__device__ __forceinline__ void cp_async16(uint32_t saddr, const void* gaddr, int srcb) {
    asm volatile("cp.async.cg.shared.global [%0], [%1], 16, %2;"
                 :: "r"(saddr), "l"(gaddr), "r"(srcb));
}
__device__ __forceinline__ void cp_commit() { asm volatile("cp.async.commit_group;" ::: "memory"); }
__device__ __forceinline__ void cp_wait1()  { asm volatile("cp.async.wait_group 1;" ::: "memory"); }
__device__ __forceinline__ void cp_wait0()  { asm volatile("cp.async.wait_group 0;" ::: "memory"); }

// fp32 -> (bf16 hi, bf16 lo) split.  which: 0=feats, 1=qkv_w, 2=proj_w
__global__ void cvt_hilo(const float* __restrict__ src, int which, int n) {
    int i = blockIdx.x * blockDim.x + threadIdx.x;
    if (i >= n) return;
    __nv_bfloat16* hi = (which == 0) ? f_hi : (which == 1) ? w_hi : pw_hi;
    __nv_bfloat16* lo = (which == 0) ? f_lo : (which == 1) ? w_lo : pw_lo;
    float x = src[i];
    __nv_bfloat16 h = __float2bfloat16(x);
    hi[i] = h;
    lo[i] = __float2bfloat16(x - __bfloat162float(h));
}

// ---------------------------------------------------------------------------
// Fused split-bf16 GEMM on mma.sync, cp.async double-buffered.
// C = A@W^T + bias via AhBh + AhBl + AlBh (fp32 acc, ~16 mantissa bits).
// Block tile 128x128, 8 warps (4x2), warp tile 32x64, K chunks of 64.
// Stage (64KB): AH@0, AL@16K, BH@32K, BL@48K, rows 128B SW-swizzled.
// SPLIT=1: A=f_hi/lo, W=w_hi/lo (768 cols) -> g_q(*QSCALE)/g_k/g_v
// SPLIT=0: A=x_hi/lo, W=pw_hi/lo (256 cols) -> Cout
// ---------------------------------------------------------------------------
template <int SPLIT>
__global__ void __launch_bounds__(256) gemm_mma(const float* __restrict__ bias,
                                                float* __restrict__ Cout, int M)
{
    extern __shared__ __align__(1024) char smem[];

    const int t    = threadIdx.x;
    const int lane = t & 31;
    const int w    = t >> 5;
    const int wm   = w & 3;            // 4 warps over M (32 rows)
    const int wn   = w >> 2;           // 2 warps over N (64 cols)
    const int m0   = blockIdx.x * 128;
    const int n0   = blockIdx.y * 128;
    const uint32_t sb = smem_u32(smem);

    const __nv_bfloat16* Ah = SPLIT ? f_hi : x_hi;
    const __nv_bfloat16* Al = SPLIT ? f_lo : x_lo;
    const __nv_bfloat16* Bh = SPLIT ? w_hi : pw_hi;
    const __nv_bfloat16* Bl = SPLIT ? w_lo : pw_lo;

    // gmem->smem: thread covers row = t>>1, 64B half = t&1 (4 x 16B)
    const int ldRow  = t >> 1;
    const int ldHalf = t & 1;
    const bool a_ok  = (m0 + ldRow) < M;
    const int aRow   = a_ok ? (m0 + ldRow) : 0;
    const int aBytes = a_ok ? 16 : 0;
    const uint32_t ldXor = (uint32_t)((ldRow & 7) * 16);

    auto prefetch = [&](int c) {
        const uint32_t stb = sb + (uint32_t)(c & 1) * 65536u;
        const char* gAh = (const char*)(Ah + (size_t)aRow * 256 + c * 64 + ldHalf * 32);
        const char* gAl = (const char*)(Al + (size_t)aRow * 256 + c * 64 + ldHalf * 32);
        const char* gBh = (const char*)(Bh + (size_t)(n0 + ldRow) * 256 + c * 64 + ldHalf * 32);
        const char* gBl = (const char*)(Bl + (size_t)(n0 + ldRow) * 256 + c * 64 + ldHalf * 32);
#pragma unroll
        for (int j = 0; j < 4; j++) {
            uint32_t so = (uint32_t)(ldRow * 128) + ((uint32_t)(ldHalf * 64 + j * 16) ^ ldXor);
            cp_async16(stb + so,          gAh + j * 16, aBytes);
            cp_async16(stb + 16384 + so,  gAl + j * 16, aBytes);
            cp_async16(stb + 32768 + so,  gBh + j * 16, 16);
            cp_async16(stb + 49152 + so,  gBl + j * 16, 16);
        }
    };

    // ldmatrix lane address components
    const int aRowIn = lane & 15;
    const int aKbAdd = (lane >> 4) * 16;
    const int bNIn   = (lane & 7) + ((lane >> 4) << 3);
    const int bKbAdd = ((lane >> 3) & 1) * 16;

    float acc[2][8][4];
#pragma unroll
    for (int f = 0; f < 2; f++)
#pragma unroll
        for (int g = 0; g < 8; g++)
#pragma unroll
            for (int e = 0; e < 4; e++) acc[f][g][e] = 0.f;

    prefetch(0);
    cp_commit();

#pragma unroll 1
    for (int c = 0; c < 4; c++) {
        if (c < 3) { prefetch(c + 1); cp_commit(); cp_wait1(); }
        else       { cp_wait0(); }
        __syncthreads();

        const uint32_t stb = sb + (uint32_t)(c & 1) * 65536u;
        const uint32_t bAH = stb, bAL = stb + 16384, bBH = stb + 32768, bBL = stb + 49152;

#pragma unroll
        for (int ks = 0; ks < 4; ks++) {
            const uint32_t kByte = (uint32_t)(ks * 32);

            uint32_t afH[2][4], afL[2][4];
#pragma unroll
            for (int f = 0; f < 2; f++) {
                int row = wm * 32 + f * 16 + aRowIn;
                uint32_t kb  = kByte + (uint32_t)aKbAdd;
                uint32_t off = (uint32_t)(row * 128) + (kb ^ (uint32_t)((row & 7) * 16));
                asm volatile("ldmatrix.sync.aligned.m8n8.x4.shared.b16 {%0,%1,%2,%3}, [%4];"
                             : "=r"(afH[f][0]), "=r"(afH[f][1]), "=r"(afH[f][2]), "=r"(afH[f][3])
                             : "r"(bAH + off));
                asm volatile("ldmatrix.sync.aligned.m8n8.x4.shared.b16 {%0,%1,%2,%3}, [%4];"
                             : "=r"(afL[f][0]), "=r"(afL[f][1]), "=r"(afL[f][2]), "=r"(afL[f][3])
                             : "r"(bAL + off));
            }

            uint32_t bfH[4][4], bfL[4][4];
#pragma unroll
            for (int g2 = 0; g2 < 4; g2++) {
                int nb = wn * 64 + g2 * 16 + bNIn;
                uint32_t kb  = kByte + (uint32_t)bKbAdd;
                uint32_t off = (uint32_t)(nb * 128) + (kb ^ (uint32_t)((nb & 7) * 16));
                asm volatile("ldmatrix.sync.aligned.m8n8.x4.shared.b16 {%0,%1,%2,%3}, [%4];"
                             : "=r"(bfH[g2][0]), "=r"(bfH[g2][1]), "=r"(bfH[g2][2]), "=r"(bfH[g2][3])
                             : "r"(bBH + off));
                asm volatile("ldmatrix.sync.aligned.m8n8.x4.shared.b16 {%0,%1,%2,%3}, [%4];"
                             : "=r"(bfL[g2][0]), "=r"(bfL[g2][1]), "=r"(bfL[g2][2]), "=r"(bfL[g2][3])
                             : "r"(bBL + off));
            }

#define MMA_BF16(ACC, AF, B0, B1)                                              \
            asm volatile(                                                      \
                "mma.sync.aligned.m16n8k16.row.col.f32.bf16.bf16.f32 "        \
                "{%0,%1,%2,%3}, {%4,%5,%6,%7}, {%8,%9}, {%0,%1,%2,%3};"       \
                : "+f"((ACC)[0]), "+f"((ACC)[1]), "+f"((ACC)[2]), "+f"((ACC)[3]) \
                : "r"((AF)[0]), "r"((AF)[1]), "r"((AF)[2]), "r"((AF)[3]),      \
                  "r"(B0), "r"(B1))

#pragma unroll
            for (int f = 0; f < 2; f++) {
#pragma unroll
                for (int g2 = 0; g2 < 4; g2++) {
                    MMA_BF16(acc[f][g2 * 2],     afH[f], bfH[g2][0], bfH[g2][1]);
                    MMA_BF16(acc[f][g2 * 2 + 1], afH[f], bfH[g2][2], bfH[g2][3]);
                    MMA_BF16(acc[f][g2 * 2],     afH[f], bfL[g2][0], bfL[g2][1]);
                    MMA_BF16(acc[f][g2 * 2 + 1], afH[f], bfL[g2][2], bfL[g2][3]);
                    MMA_BF16(acc[f][g2 * 2],     afL[f], bfH[g2][0], bfH[g2][1]);
                    MMA_BF16(acc[f][g2 * 2 + 1], afL[f], bfH[g2][2], bfH[g2][3]);
                }
            }
#undef MMA_BF16
        }
        if (c < 3) __syncthreads();
    }

    // ---- epilogue ----
    const int rBase = m0 + wm * 32 + (lane >> 2);
    const int cIn   = (lane & 3) * 2;

    const int sect = SPLIT ? (n0 >> 8) : 0;
    float* dstBase = SPLIT ? ((sect == 0) ? g_q : (sect == 1) ? g_k : g_v) : Cout;
    const float mult = (SPLIT && sect == 0) ? QSCALE : 1.0f;
    const int nLocal = SPLIT ? (n0 & 255) : n0;

#pragma unroll
    for (int f = 0; f < 2; f++) {
#pragma unroll
        for (int g = 0; g < 8; g++) {
            const int colFull = n0 + wn * 64 + g * 8 + cIn;
            const int colOut  = nLocal + wn * 64 + g * 8 + cIn;
            const float b0 = bias[colFull], b1 = bias[colFull + 1];
#pragma unroll
            for (int h = 0; h < 2; h++) {
                const int row = rBase + f * 16 + h * 8;
                if (row < M) {
                    float2 ov;
                    ov.x = (acc[f][g][h * 2 + 0] + b0) * mult;
                    ov.y = (acc[f][g][h * 2 + 1] + b1) * mult;
                    *reinterpret_cast<float2*>(dstBase + (size_t)row * 256 + colOut) = ov;
                }
            }
        }
    }
}

// ---------------------------------------------------------------------------
// Attention: warp per (point, head). No smem, no __syncthreads.
// Lanes: (j = lane&15, half = lane>>4) for logits; lane = dim for V phase.
// ---------------------------------------------------------------------------
__global__ void __launch_bounds__(256) attn_kernel(const int* __restrict__ index_1, int M)
{
    const int gw   = (blockIdx.x * 256 + threadIdx.x) >> 5;   // global warp id
    const int i    = gw >> 3;
    const int h    = gw & 7;
    const int lane = threadIdx.x & 31;
    if (i >= M) return;

    int nj = 0;
    if (lane < 16) nj = __ldg(index_1 + i * KNBR + lane);

    const int jj   = lane & 15;
    const int half = lane >> 4;
    const int nbrj = __shfl_sync(0xffffffffu, nj, jj);

    // logit: lane pair (jj, half) covers dims [half*16, half*16+16)
    const float4* kr = reinterpret_cast<const float4*>(g_k + (size_t)nbrj * 256 + h * 32 + half * 16);
    const float4* qr = reinterpret_cast<const float4*>(g_q + (size_t)i * 256 + h * 32 + half * 16);
    float dot = 0.f;
#pragma unroll
    for (int d4 = 0; d4 < 4; d4++) {
        float4 kv = kr[d4];
        float4 qv = qr[d4];
        dot += qv.x * kv.x + qv.y * kv.y + qv.z * kv.z + qv.w * kv.w;
    }
    dot += __shfl_xor_sync(0xffffffffu, dot, 16);

    float mx = dot;
#pragma unroll
    for (int o = 8; o > 0; o >>= 1) mx = fmaxf(mx, __shfl_xor_sync(0xffffffffu, mx, o));
    float e = __expf(dot - mx);
    float s = e;
#pragma unroll
    for (int o = 8; o > 0; o >>= 1) s += __shfl_xor_sync(0xffffffffu, s, o);
    const float wgt = e / s;

    // weighted V: lane = dim d
    const float* vb = g_v + h * 32 + lane;
    float acc = 0.f;
#pragma unroll
    for (int j = 0; j < 16; j++) {
        float wj = __shfl_sync(0xffffffffu, wgt, j);
        int   n  = __shfl_sync(0xffffffffu, nj, j);
        acc += wj * vb[(size_t)n * 256];
    }

    __nv_bfloat16 hv = __float2bfloat16(acc);
    const size_t xo = (size_t)i * 256 + h * 32 + lane;
    x_hi[xo] = hv;
    x_lo[xo] = __float2bfloat16(acc - __bfloat162float(hv));
}

// ---------------------------------------------------------------------------
extern "C" void kernel_launch(void* const* d_in, const int* in_sizes, int n_in,
                              void* d_out, int out_size)
{
    const float* feats   = (const float*)d_in[0];
    const int*   index_1 = (const int*)d_in[3];

    int iw = -1;
    for (int i = 0; i < n_in; i++)
        if (in_sizes[i] == 3 * DIMC * DIMC) { iw = i; break; }
    const float* qkv_w  = (const float*)d_in[iw];
    const float* qkv_b  = (const float*)d_in[iw + 1];
    const float* proj_w = (const float*)d_in[iw + 2];
    const float* proj_b = (const float*)d_in[iw + 3];

    const int M = in_sizes[0] / DIMC;   // 50000

    const int SMEM_BYTES = 131072;      // 2 stages x 64KB
    cudaFuncSetAttribute(gemm_mma<1>, cudaFuncAttributeMaxDynamicSharedMemorySize, SMEM_BYTES);
    cudaFuncSetAttribute(gemm_mma<0>, cudaFuncAttributeMaxDynamicSharedMemorySize, SMEM_BYTES);

    cvt_hilo<<<(M * DIMC + 255) / 256, 256>>>(feats, 0, M * DIMC);
    cvt_hilo<<<(768 * 256 + 255) / 256, 256>>>(qkv_w, 1, 768 * 256);
    cvt_hilo<<<(256 * 256 + 255) / 256, 256>>>(proj_w, 2, 256 * 256);

    dim3 g_qkv((M + 127) / 128, 6);     // 768 output cols
    gemm_mma<1><<<g_qkv, 256, SMEM_BYTES>>>(qkv_b, nullptr, M);

    attn_kernel<<<M, 256>>>(index_1, M);

    dim3 g_proj((M + 127) / 128, 2);    // 256 output cols
    gemm_mma<0><<<g_proj, 256, SMEM_BYTES>>>(proj_b, (float*)d_out, M);
}